// round 6
// baseline (speedup 1.0000x reference)
#include <cuda_runtime.h>
#include <cstdint>

// CenterLoss: mean_i ||x_i - centers[labels_i]||^2
//   = mean( ||x||^2 + ||c||^2 - 2 x.c )
// x: [4096, 512] f32, centers: [7001, 512] f32, labels: [4096] i32 -> out: [1] f32
//
// Strategy: cp.async.bulk (TMA path) stages rows into SMEM to break the
// LDG demand-side bandwidth ceiling (~1.8 TB/s observed across all LDG
// variants with DRAM only ~22% busy).

#define BATCH 4096
#define DIM 512
#define VEC (DIM / 4)          // 128 float4 per row
#define ROW_BYTES 2048         // 512 f32
#define NBLK 256
#define BLOCK 256
#define SPB 16                 // samples per CTA

// SMEM layout (dynamic):
//   [0, 32K)      : 16 x rows
//   [32K, 64K)    : 16 gathered center rows
//   [64K, 64K+8)  : mbarrier
#define SM_X 0
#define SM_C 32768
#define SM_MBAR 65536
#define SMEM_BYTES (65536 + 128)

__device__ float g_slots[NBLK * 32];   // one slot per CTA, 128B apart
__device__ unsigned int g_count = 0;

__device__ __forceinline__ uint32_t smem_u32(const void* p) {
    uint32_t a;
    asm("{ .reg .u64 t; cvta.to.shared.u64 t, %1; cvt.u32.u64 %0, t; }"
        : "=r"(a) : "l"(p));
    return a;
}

__global__ __launch_bounds__(BLOCK, 3)
void center_loss_kernel(const float* __restrict__ x,
                        const float* __restrict__ c,
                        const int4* __restrict__ labels4,
                        float* __restrict__ out)
{
    extern __shared__ char smem[];
    const int t = threadIdx.x;        // 0..255
    const int b = blockIdx.x;
    const uint32_t sbase = smem_u32(smem);
    const uint32_t mbar = sbase + SM_MBAR;

    if (t == 0) {
        asm volatile("mbarrier.init.shared.b64 [%0], 1;" :: "r"(mbar) : "memory");
        asm volatile("fence.proxy.async.shared::cta;" ::: "memory");
    }
    __syncthreads();

    if (t == 0) {
        // Expect the full 64 KB, then post copies.
        asm volatile("mbarrier.arrive.expect_tx.shared.b64 _, [%0], %1;"
                     :: "r"(mbar), "r"(65536u) : "memory");
        // x rows are contiguous: one 32 KB bulk copy.
        const char* xsrc = (const char*)x + (size_t)b * SPB * ROW_BYTES;
        asm volatile(
            "cp.async.bulk.shared::cta.global.mbarrier::complete_tx::bytes "
            "[%0], [%1], %2, [%3];"
            :: "r"(sbase + SM_X), "l"(xsrc), "r"((uint32_t)(SPB * ROW_BYTES)),
               "r"(mbar) : "memory");
        // Labels for this CTA: 4 independent int4 loads (one L2/DRAM trip).
        int4 l0 = __ldg(&labels4[b * 4 + 0]);
        int4 l1 = __ldg(&labels4[b * 4 + 1]);
        int4 l2 = __ldg(&labels4[b * 4 + 2]);
        int4 l3 = __ldg(&labels4[b * 4 + 3]);
        int labs[SPB] = { l0.x, l0.y, l0.z, l0.w,  l1.x, l1.y, l1.z, l1.w,
                          l2.x, l2.y, l2.z, l2.w,  l3.x, l3.y, l3.z, l3.w };
        // 16 gathered 2 KB center-row copies.
#pragma unroll
        for (int s = 0; s < SPB; s++) {
            const char* csrc = (const char*)c + (size_t)labs[s] * ROW_BYTES;
            asm volatile(
                "cp.async.bulk.shared::cta.global.mbarrier::complete_tx::bytes "
                "[%0], [%1], %2, [%3];"
                :: "r"(sbase + SM_C + s * ROW_BYTES), "l"(csrc),
                   "r"((uint32_t)ROW_BYTES), "r"(mbar) : "memory");
        }
    }

    // All threads wait for the 64 KB to land (parity 0).
    {
        uint32_t done;
        asm volatile(
            "{\n\t.reg .pred p;\n\t"
            "mbarrier.try_wait.parity.acquire.cta.shared::cta.b64 p, [%1], 0;\n\t"
            "selp.b32 %0, 1, 0, p;\n\t}"
            : "=r"(done) : "r"(mbar) : "memory");
        if (!done) {
            asm volatile(
                "{\n\t.reg .pred P1;\n\t"
                "W%=:\n\t"
                "mbarrier.try_wait.parity.acquire.cta.shared::cta.b64 P1, [%0], 0, 0x989680;\n\t"
                "@P1 bra.uni D%=;\n\t"
                "bra.uni W%=;\n\t"
                "D%=:\n\t}"
                :: "r"(mbar) : "memory");
        }
    }

    // Compute from SMEM: warp w handles samples 2w and 2w+1.
    const int w = t >> 5;
    const int lane = t & 31;
    const float4* sx = (const float4*)(smem + SM_X);
    const float4* sc = (const float4*)(smem + SM_C);

    float axx = 0.0f, acc_ = 0.0f, axc = 0.0f;
#pragma unroll
    for (int k = 0; k < 2; k++) {
        const int s = 2 * w + k;
#pragma unroll
        for (int i = 0; i < 4; i++) {
            float4 xv = sx[s * VEC + i * 32 + lane];
            float4 cv = sc[s * VEC + i * 32 + lane];
            axx = fmaf(xv.x, xv.x, axx);
            axx = fmaf(xv.y, xv.y, axx);
            axx = fmaf(xv.z, xv.z, axx);
            axx = fmaf(xv.w, xv.w, axx);
            acc_ = fmaf(cv.x, cv.x, acc_);
            acc_ = fmaf(cv.y, cv.y, acc_);
            acc_ = fmaf(cv.z, cv.z, acc_);
            acc_ = fmaf(cv.w, cv.w, acc_);
            axc = fmaf(xv.x, cv.x, axc);
            axc = fmaf(xv.y, cv.y, axc);
            axc = fmaf(xv.z, cv.z, axc);
            axc = fmaf(xv.w, cv.w, axc);
        }
    }
    float acc = axx + acc_ - 2.0f * axc;

    // Warp reduce
#pragma unroll
    for (int o = 16; o; o >>= 1) acc += __shfl_xor_sync(0xffffffffu, acc, o);

    __shared__ float ws[BLOCK / 32];
    if (lane == 0) ws[w] = acc;
    __syncthreads();

    // Warp 0: CTA sum -> private slot store; acq_rel ticket orders it.
    if (t < 32) {
        unsigned int v = 0;
        if (t == 0) {
            float p = 0.0f;
#pragma unroll
            for (int i = 0; i < BLOCK / 32; i++) p += ws[i];
            g_slots[b * 32] = p;
            asm volatile("atom.add.acq_rel.gpu.global.u32 %0, [%1], 1;"
                         : "=r"(v) : "l"(&g_count) : "memory");
        }
        v = __shfl_sync(0xffffffffu, v, 0);
        if (v == NBLK - 1) {           // last CTA: all slot stores visible
            float vsum = 0.0f;
#pragma unroll
            for (int k = 0; k < NBLK / 32; k++) {
                float s;
                asm volatile("ld.global.cg.f32 %0, [%1];"
                             : "=f"(s) : "l"(&g_slots[(t + k * 32) * 32]) : "memory");
                vsum += s;
            }
#pragma unroll
            for (int o = 16; o; o >>= 1) vsum += __shfl_xor_sync(0xffffffffu, vsum, o);
            if (t == 0) {
                out[0] = vsum * (1.0f / (float)BATCH);
                g_count = 0u;          // self-reset for next graph replay
            }
        }
    }
}

extern "C" void kernel_launch(void* const* d_in, const int* in_sizes, int n_in,
                              void* d_out, int out_size)
{
    const float* x = (const float*)d_in[0];
    const float* c = (const float*)d_in[1];
    const int4* labels4 = (const int4*)d_in[2];
    float* out = (float*)d_out;
    cudaFuncSetAttribute(center_loss_kernel,
                         cudaFuncAttributeMaxDynamicSharedMemorySize, SMEM_BYTES);
    center_loss_kernel<<<NBLK, BLOCK, SMEM_BYTES>>>(x, c, labels4, out);
}

// round 8
// speedup vs baseline: 1.0772x; 1.0772x over previous
#include <cuda_runtime.h>

// CenterLoss: mean_i ||x_i - centers[labels_i]||^2
//   = mean( ||x||^2 + ||c||^2 - 2 x.c )
// x: [4096, 512] f32, centers: [7001, 512] f32, labels: [4096] i32 -> out: [1] f32

#define BATCH 4096
#define DIM 512
#define VEC (DIM / 4)     // 128 float4 per row
#define NBLK 512
#define BLOCK 256
#define SPB 8             // samples per block (4 per 128-thread half) -> exact balance

__device__ float g_accum = 0.0f;       // single pre-scaled accumulator
__device__ unsigned int g_count = 0;

__global__ __launch_bounds__(BLOCK, 4)
void center_loss_kernel(const float4* __restrict__ x,
                        const float4* __restrict__ c,
                        const int4* __restrict__ labels4,
                        float* __restrict__ out)
{
    const int t = threadIdx.x;        // 0..255
    const int b = blockIdx.x;
    const int h = t >> 7;             // half 0/1 -> samples [4h, 4h+4)
    const int lane128 = t & 127;      // float4 lane within a row
    const int base = b * SPB + h * 4;

    // One int4 per half: the dependent center gather issues ASAP after this.
    const int4 lv = __ldg(&labels4[b * 2 + h]);
    const int labs[4] = { lv.x, lv.y, lv.z, lv.w };

    // Decomposed accumulation: each loaded float4 consumed independently
    // (tiny live ranges -> ptxas front-batches all 8 data loads).
    float axx = 0.0f, acc_ = 0.0f, axc = 0.0f;
#pragma unroll
    for (int s = 0; s < 4; s++) {
        float4 xv = x[(base + s) * VEC + lane128];
        axx = fmaf(xv.x, xv.x, axx);
        axx = fmaf(xv.y, xv.y, axx);
        axx = fmaf(xv.z, xv.z, axx);
        axx = fmaf(xv.w, xv.w, axx);
        float4 cv = c[labs[s] * VEC + lane128];
        acc_ = fmaf(cv.x, cv.x, acc_);
        acc_ = fmaf(cv.y, cv.y, acc_);
        acc_ = fmaf(cv.z, cv.z, acc_);
        acc_ = fmaf(cv.w, cv.w, acc_);
        axc = fmaf(xv.x, cv.x, axc);
        axc = fmaf(xv.y, cv.y, axc);
        axc = fmaf(xv.z, cv.z, axc);
        axc = fmaf(xv.w, cv.w, axc);
    }
    float acc = axx + acc_ - 2.0f * axc;

    // Warp reduce
#pragma unroll
    for (int o = 16; o; o >>= 1) acc += __shfl_xor_sync(0xffffffffu, acc, o);

    __shared__ float ws[BLOCK / 32];
    if ((t & 31) == 0) ws[t >> 5] = acc;
    __syncthreads();

    // Thread 0 only: one pre-scaled RED + acq_rel ticket; last CTA reads 1 float.
    if (t == 0) {
        float p = 0.0f;
#pragma unroll
        for (int w = 0; w < BLOCK / 32; w++) p += ws[w];
        // Posted reduction (no return), pre-scaled so accumulator == mean.
        asm volatile("red.add.relaxed.gpu.global.f32 [%0], %1;"
                     :: "l"(&g_accum), "f"(p * (1.0f / (float)BATCH))
                     : "memory");
        // Release orders the RED above; acquire covers the read below.
        unsigned int v;
        asm volatile("atom.add.acq_rel.gpu.global.u32 %0, [%1], 1;"
                     : "=r"(v) : "l"(&g_count) : "memory");
        const bool last = (v == NBLK - 1);
        // Straight-line predicated finale (avoid BSSY/BSYNC): safe because
        // only the last-arriving CTA has `last` set.
        float s = 0.0f;
        if (last) {
            asm volatile("ld.global.cg.f32 %0, [%1];"
                         : "=f"(s) : "l"(&g_accum) : "memory");
            out[0] = s;
            asm volatile("st.global.cg.f32 [%0], 0f00000000;"
                         :: "l"(&g_accum) : "memory");   // reset accumulator
            asm volatile("st.global.cg.u32 [%0], 0;"
                         :: "l"(&g_count) : "memory");   // reset ticket
        }
    }
}

extern "C" void kernel_launch(void* const* d_in, const int* in_sizes, int n_in,
                              void* d_out, int out_size)
{
    const float4* x = (const float4*)d_in[0];
    const float4* c = (const float4*)d_in[1];
    const int4* labels4 = (const int4*)d_in[2];
    float* out = (float*)d_out;
    center_loss_kernel<<<NBLK, BLOCK>>>(x, c, labels4, out);
}